// round 8
// baseline (speedup 1.0000x reference)
#include <cuda_runtime.h>
#include <cuda_bf16.h>

// HierarchicalSoftmax fused kernel, round 7.
// One warp per sample; two 16-lane halves each handle one tree node per slot
// (lane owns 8 embedding floats). All 18 W-row loads front-batched (MLP=18).
// Dot partials stay packed f32x2 end-to-end: loop = 4xFFMA2 + 1 packed add +
// STS.64; transposed epilogue reduces with packed adds, one BCE block for all
// 17 nodes, one butterfly, deterministic grid reduction.
//
// Inputs (metadata order):
//   d_in[0]: embeddings float32 [B, E]   (B=16384, E=128)
//   d_in[1]: word_idx   int32   [B]
//   d_in[2]: W          float32 [V-1, E] (V=131072)
//   d_in[3]: b          float32 [V-1]
// Output: float32 scalar = mean over B of sum over 17 path nodes of BCE.

#define HS_D 17
#define TPB  256
#define WPB  8
#define MAX_BLOCKS 8192
#define NSLOT 9              // slots per half; 9*2 = 18 >= 17 nodes (1 dup)
#define SLOT_BYTES 144       // 16 lanes * 8B packed partial + 16B pad (16B-aligned)
#define WARP_BYTES (2 * NSLOT * SLOT_BYTES)   // 2592 B per warp

typedef unsigned long long u64;

__device__ float        g_hs_partials[MAX_BLOCKS];
__device__ unsigned int g_hs_count = 0;   // self-resetting ticket

__device__ __forceinline__ u64 ffma2(u64 a, u64 b, u64 c)
{
    u64 d;
    asm("fma.rn.f32x2 %0, %1, %2, %3;" : "=l"(d) : "l"(a), "l"(b), "l"(c));
    return d;
}
__device__ __forceinline__ u64 addf2(u64 a, u64 b)
{
    u64 d;
    asm("add.rn.f32x2 %0, %1, %2;" : "=l"(d) : "l"(a), "l"(b));
    return d;
}

__global__ __launch_bounds__(TPB)
void hs_fused_kernel(const float*  __restrict__ emb,
                     const int*    __restrict__ word_idx,
                     const float4* __restrict__ W4,
                     const float*  __restrict__ bias,
                     float*        __restrict__ out,
                     int B, int Vm1, float invB)
{
    const int warp  = blockIdx.x * WPB + (threadIdx.x >> 5);
    const int wslot = threadIdx.x >> 5;
    const int lane  = threadIdx.x & 31;
    const int half  = lane >> 4;      // which node of the slot-pair this lane serves
    const int hl    = lane & 15;      // lane within the 16-lane half

    __shared__ __align__(16) char spart[WPB * WARP_BYTES];
    char* const mybase = spart + wslot * WARP_BYTES;

    float warp_sum = 0.0f;

    if (warp < B) {
        const char* __restrict__ Wb = reinterpret_cast<const char*>(W4);

        // Lane owns embedding floats [hl*8, hl*8+8) as 2 x 16B (4 f32x2 pairs).
        const ulonglong2* erow = reinterpret_cast<const ulonglong2*>(emb)
                               + (size_t)warp * 32 + hl * 2;
        const ulonglong2 eA = erow[0];
        const ulonglong2 eB = erow[1];

        // 1-based leaf heap index: W-node at depth d = (leaf1 >> (d+1)) - 1;
        // direction bit at depth d = ((leaf1 >> d) & 1) ^ 1.
        const unsigned leaf1 = (unsigned)__ldg(&word_idx[warp])
                             + (unsigned)(Vm1 + 1);

        // Byte offset of this lane within a (node+1)-based row block:
        // W row n starts at n*512 = ((n+1)<<9) - 512.
        const int laneoff = hl * 32 - 512;

        // ---- pass 1: issue ALL W loads back-to-back (MLP = 18) ----
        ulonglong2 wA[NSLOT], wB[NSLOT];
        #pragma unroll
        for (int j = 0; j < NSLOT; ++j) {
            const int slot = 2 * j + half;                      // 0..17
            const int idx  = (slot < HS_D) ? slot : (HS_D - 1); // dup root on 17
            const size_t off = ((size_t)(leaf1 >> (idx + 1)) << 9) + laneoff;
            const ulonglong2* wr = reinterpret_cast<const ulonglong2*>(Wb + off);
            wA[j] = __ldg(wr);
            wB[j] = __ldg(wr + 1);
        }

        // ---- pass 2: packed FMA + packed add + STS.64 ----
        u64* const prow = reinterpret_cast<u64*>(mybase);
        #pragma unroll
        for (int j = 0; j < NSLOT; ++j) {
            const int slot = 2 * j + half;
            u64 p0 = ffma2(wA[j].x, eA.x, 0ull);
            u64 p1 = ffma2(wA[j].y, eA.y, 0ull);
            p0 = ffma2(wB[j].x, eB.x, p0);
            p1 = ffma2(wB[j].y, eB.y, p1);
            prow[slot * (SLOT_BYTES / 8) + hl] = addf2(p0, p1);
        }
        __syncwarp();

        // ---- transposed epilogue: lane d reduces node d's 16 packed pairs ----
        const int d = (lane < HS_D) ? lane : (HS_D - 1);   // clamped duplicate
        const ulonglong2* pv =
            reinterpret_cast<const ulonglong2*>(mybase + d * SLOT_BYTES);
        const ulonglong2 q0 = pv[0];
        const ulonglong2 q1 = pv[1];
        const ulonglong2 q2 = pv[2];
        const ulonglong2 q3 = pv[3];
        const ulonglong2 q4 = pv[4];
        const ulonglong2 q5 = pv[5];
        const ulonglong2 q6 = pv[6];
        const ulonglong2 q7 = pv[7];

        u64 r0 = addf2(addf2(q0.x, q0.y), addf2(q1.x, q1.y));
        u64 r1 = addf2(addf2(q2.x, q2.y), addf2(q3.x, q3.y));
        u64 r2 = addf2(addf2(q4.x, q4.y), addf2(q5.x, q5.y));
        u64 r3 = addf2(addf2(q6.x, q6.y), addf2(q7.x, q7.y));
        u64 rt = addf2(addf2(r0, r1), addf2(r2, r3));

        float rlo, rhi;
        asm("mov.b64 {%0,%1}, %2;" : "=f"(rlo), "=f"(rhi) : "l"(rt));
        const float dot = rlo + rhi;

        const int   n = (int)((leaf1 >> (d + 1)) - 1u);
        const float s = dot + __ldg(&bias[n]);
        const float t = (float)(((leaf1 >> d) & 1u) ^ 1u);
        float bce = fmaxf(s, 0.0f) - s * t + __logf(1.0f + __expf(-fabsf(s)));
        if (lane >= HS_D) bce = 0.0f;

        // One butterfly for the whole sample.
        bce += __shfl_xor_sync(0xffffffffu, bce, 16);
        bce += __shfl_xor_sync(0xffffffffu, bce, 8);
        bce += __shfl_xor_sync(0xffffffffu, bce, 4);
        bce += __shfl_xor_sync(0xffffffffu, bce, 2);
        bce += __shfl_xor_sync(0xffffffffu, bce, 1);
        warp_sum = bce;
    }

    // ---- block reduction + last-block grid reduction (deterministic) ----
    __shared__ float sacc[WPB];
    __shared__ bool  is_last;
    if (lane == 0) sacc[wslot] = warp_sum;
    __syncthreads();
    if (threadIdx.x == 0) {
        float ssum = 0.0f;
        #pragma unroll
        for (int i = 0; i < WPB; ++i) ssum += sacc[i];
        g_hs_partials[blockIdx.x] = ssum;
        __threadfence();
        unsigned tk = atomicInc(&g_hs_count, gridDim.x - 1);
        is_last = (tk == gridDim.x - 1);
    }
    __syncthreads();

    if (is_last) {
        float a = 0.0f;
        for (int i = threadIdx.x; i < (int)gridDim.x; i += TPB)
            a += g_hs_partials[i];
        __shared__ float red[TPB];
        red[threadIdx.x] = a;
        __syncthreads();
        #pragma unroll
        for (int ofs = TPB / 2; ofs > 0; ofs >>= 1) {
            if (threadIdx.x < ofs) red[threadIdx.x] += red[threadIdx.x + ofs];
            __syncthreads();
        }
        if (threadIdx.x == 0) out[0] = red[0] * invB;
    }
}

extern "C" void kernel_launch(void* const* d_in, const int* in_sizes, int n_in,
                              void* d_out, int out_size)
{
    const float*  emb      = (const float*) d_in[0];
    const int*    word_idx = (const int*)   d_in[1];
    const float4* W4       = (const float4*)d_in[2];
    const float*  bias     = (const float*) d_in[3];
    float* out = (float*)d_out;

    const int B   = in_sizes[1];   // 16384
    const int Vm1 = in_sizes[3];   // V-1 = 131071

    int nblocks = (B + WPB - 1) / WPB;            // 2048
    if (nblocks > MAX_BLOCKS) nblocks = MAX_BLOCKS;

    hs_fused_kernel<<<nblocks, TPB>>>(emb, word_idx, W4, bias, out,
                                      B, Vm1, 1.0f / (float)B);
}

// round 9
// speedup vs baseline: 1.2073x; 1.2073x over previous
#include <cuda_runtime.h>
#include <cuda_bf16.h>

// HierarchicalSoftmax fused kernel, round 8.
// Base = round-6 structure (best so far). Delta: TPB=128 with
// __launch_bounds__(128,1) + a __syncwarp() fence between the load pass and
// the compute pass, forcing ptxas to keep all 18 W-row loads in flight
// (true MLP=18, one exposed memory latency per warp).
//
// Inputs (metadata order):
//   d_in[0]: embeddings float32 [B, E]   (B=16384, E=128)
//   d_in[1]: word_idx   int32   [B]
//   d_in[2]: W          float32 [V-1, E] (V=131072)
//   d_in[3]: b          float32 [V-1]
// Output: float32 scalar = mean over B of sum over 17 path nodes of BCE.

#define HS_D 17
#define TPB  128
#define WPB  4
#define MAX_BLOCKS 8192
#define NSLOT 9             // slots per half; 9*2 = 18 >= 17 nodes (1 dup)
#define PSTRIDE 20          // floats per node-slot (16 partials + 4 pad; 80B, 16B-aligned)
#define ROW_U2 32           // 128 floats per row = 32 ulonglong2 (16B each)

typedef unsigned long long u64;

__device__ float        g_hs_partials[MAX_BLOCKS];
__device__ unsigned int g_hs_count = 0;   // self-resetting ticket

__device__ __forceinline__ u64 ffma2(u64 a, u64 b, u64 c)
{
    u64 d;
    asm("fma.rn.f32x2 %0, %1, %2, %3;" : "=l"(d) : "l"(a), "l"(b), "l"(c));
    return d;
}

__global__ __launch_bounds__(TPB, 1)
void hs_fused_kernel(const float*  __restrict__ emb,
                     const int*    __restrict__ word_idx,
                     const float4* __restrict__ W4,
                     const float*  __restrict__ bias,
                     float*        __restrict__ out,
                     int B, int Vm1, float invB)
{
    const int warp  = blockIdx.x * WPB + (threadIdx.x >> 5);
    const int wslot = threadIdx.x >> 5;
    const int lane  = threadIdx.x & 31;
    const int half  = lane >> 4;      // which node of the slot-pair this lane serves
    const int hl    = lane & 15;      // lane within the 16-lane half

    __shared__ __align__(16) float spart[WPB][2 * NSLOT * PSTRIDE];

    float warp_sum = 0.0f;

    if (warp < B) {
        const char* __restrict__ Wb = reinterpret_cast<const char*>(W4);

        // Lane owns embedding floats [hl*8, hl*8+8) as 2 x 16B loads.
        const ulonglong2* erow = reinterpret_cast<const ulonglong2*>(emb)
                               + (size_t)warp * ROW_U2 + hl * 2;
        const ulonglong2 eA = erow[0];
        const ulonglong2 eB = erow[1];

        // 1-based leaf heap index: W-node at depth d = (leaf1 >> (d+1)) - 1;
        // direction bit at depth d = ((leaf1 >> d) & 1) ^ 1.
        const unsigned leaf1 = (unsigned)__ldg(&word_idx[warp])
                             + (unsigned)(Vm1 + 1);

        // Lane byte offset inside a (node+1)-indexed 512B row block:
        // row n starts at n*512 = ((n+1) << 9) - 512.
        const int laneoff = hl * 32 - 512;

        // ---- pass 1: issue ALL W loads back-to-back ----
        ulonglong2 wA[NSLOT], wB[NSLOT];
        #pragma unroll
        for (int j = 0; j < NSLOT; ++j) {
            const int slot = 2 * j + half;                      // 0..17
            const int idx  = (slot < HS_D) ? slot : (HS_D - 1); // dup root on 17
            const size_t off = ((size_t)(leaf1 >> (idx + 1)) << 9) + laneoff;
            const ulonglong2* wr = reinterpret_cast<const ulonglong2*>(Wb + off);
            wA[j] = __ldg(wr);
            wB[j] = __ldg(wr + 1);
        }

        // Execution barrier: ptxas cannot hoist the consumers above this, so
        // all 18 load results stay live => true MLP=18 per warp.
        __syncwarp();

        // ---- pass 2: packed FMA + STS.32 (R6 form) ----
        #pragma unroll
        for (int j = 0; j < NSLOT; ++j) {
            const int slot = 2 * j + half;
            u64 p0 = ffma2(wA[j].x, eA.x, 0ull);
            u64 p1 = ffma2(wA[j].y, eA.y, 0ull);
            p0 = ffma2(wB[j].x, eB.x, p0);
            p1 = ffma2(wB[j].y, eB.y, p1);

            float p0l, p0h, p1l, p1h;
            asm("mov.b64 {%0,%1}, %2;" : "=f"(p0l), "=f"(p0h) : "l"(p0));
            asm("mov.b64 {%0,%1}, %2;" : "=f"(p1l), "=f"(p1h) : "l"(p1));
            spart[wslot][slot * PSTRIDE + hl] = (p0l + p0h) + (p1l + p1h);
        }
        __syncwarp();

        // ---- transposed epilogue: lane d reduces node d's 16 partials ----
        const int d = (lane < HS_D) ? lane : (HS_D - 1);   // clamped duplicate
        const float4* pv = reinterpret_cast<const float4*>(
                               &spart[wslot][d * PSTRIDE]);
        const float4 a0 = pv[0];
        const float4 a1 = pv[1];
        const float4 a2 = pv[2];
        const float4 a3 = pv[3];
        const float dot = ((a0.x + a0.y) + (a0.z + a0.w))
                        + ((a1.x + a1.y) + (a1.z + a1.w))
                        + ((a2.x + a2.y) + (a2.z + a2.w))
                        + ((a3.x + a3.y) + (a3.z + a3.w));

        const int   n = (int)((leaf1 >> (d + 1)) - 1u);
        const float s = dot + __ldg(&bias[n]);
        const float t = (float)(((leaf1 >> d) & 1u) ^ 1u);
        float bce = fmaxf(s, 0.0f) - s * t + __logf(1.0f + __expf(-fabsf(s)));
        if (lane >= HS_D) bce = 0.0f;

        // One butterfly for the whole sample.
        bce += __shfl_xor_sync(0xffffffffu, bce, 16);
        bce += __shfl_xor_sync(0xffffffffu, bce, 8);
        bce += __shfl_xor_sync(0xffffffffu, bce, 4);
        bce += __shfl_xor_sync(0xffffffffu, bce, 2);
        bce += __shfl_xor_sync(0xffffffffu, bce, 1);
        warp_sum = bce;
    }

    // ---- block reduction + last-block grid reduction (deterministic) ----
    __shared__ float sacc[WPB];
    __shared__ bool  is_last;
    if (lane == 0) sacc[wslot] = warp_sum;
    __syncthreads();
    if (threadIdx.x == 0) {
        float ssum = 0.0f;
        #pragma unroll
        for (int i = 0; i < WPB; ++i) ssum += sacc[i];
        g_hs_partials[blockIdx.x] = ssum;
        __threadfence();
        unsigned tk = atomicInc(&g_hs_count, gridDim.x - 1);
        is_last = (tk == gridDim.x - 1);
    }
    __syncthreads();

    if (is_last) {
        float a = 0.0f;
        for (int i = threadIdx.x; i < (int)gridDim.x; i += TPB)
            a += g_hs_partials[i];
        __shared__ float red[TPB];
        red[threadIdx.x] = a;
        __syncthreads();
        #pragma unroll
        for (int ofs = TPB / 2; ofs > 0; ofs >>= 1) {
            if (threadIdx.x < ofs) red[threadIdx.x] += red[threadIdx.x + ofs];
            __syncthreads();
        }
        if (threadIdx.x == 0) out[0] = red[0] * invB;
    }
}

extern "C" void kernel_launch(void* const* d_in, const int* in_sizes, int n_in,
                              void* d_out, int out_size)
{
    const float*  emb      = (const float*) d_in[0];
    const int*    word_idx = (const int*)   d_in[1];
    const float4* W4       = (const float4*)d_in[2];
    const float*  bias     = (const float*) d_in[3];
    float* out = (float*)d_out;

    const int B   = in_sizes[1];   // 16384
    const int Vm1 = in_sizes[3];   // V-1 = 131071

    int nblocks = (B + WPB - 1) / WPB;            // 4096
    if (nblocks > MAX_BLOCKS) nblocks = MAX_BLOCKS;

    hs_fused_kernel<<<nblocks, TPB>>>(emb, word_idx, W4, bias, out,
                                      B, Vm1, 1.0f / (float)B);
}